// round 8
// baseline (speedup 1.0000x reference)
#include <cuda_runtime.h>

#define DD 512
#define NN 128
#define TPB 512
#define BB 16
#define NBLK (DD / BB)
#define TINYF 1e-30f

// ---- packed f32x2 helpers (Blackwell FFMA2) ----
__device__ __forceinline__ unsigned long long fma2(unsigned long long a,
                                                   unsigned long long b,
                                                   unsigned long long c) {
    unsigned long long d;
    asm("fma.rn.f32x2 %0, %1, %2, %3;" : "=l"(d) : "l"(a), "l"(b), "l"(c));
    return d;
}
__device__ __forceinline__ float lo2(unsigned long long v) {
    return __uint_as_float((unsigned)v);
}
__device__ __forceinline__ float hi2(unsigned long long v) {
    return __uint_as_float((unsigned)(v >> 32));
}
__device__ __forceinline__ unsigned long long pack2(float x, float y) {
    unsigned long long d;
    asm("mov.b64 %0, {%1, %2};" : "=l"(d) : "f"(x), "f"(y));
    return d;
}

// Blocked Woodbury sampler, block size b=16 — bounded unrolling so the
// B-register tile (rb2[16]) NEVER spills. Rounds 6/7 regressed purely because
// full unroll of the 16-iteration SMEM sweeps hoisted ~128 regs of operands,
// pushing past the 128/thread cap and spilling rb2 to local (HBM 240 GB/s).
//
// Per block (steps j = 0..15, global i = I0+j):
//   phase1: Y = B * UP_blk            (decision-independent GEMM)
//   phase2: G[j][m] = up_j . y_m      (16x16 small GEMM)
//   warp-0 recursion (SMEM-resident t-vectors, lane scalars only)
//   phaseQ: Q rows = Y * t_j
//   phase4: B += Q diag(piv) Q^T      (rank-16 fold)
__global__ __launch_bounds__(TPB, 1)
void slater_sampler_kernel(const float* __restrict__ P,
                           const float* __restrict__ uin,
                           float* __restrict__ out,
                           int out_size)
{
    __shared__ __align__(16) float sh_UP[BB][NN];
    __shared__ __align__(16) float sh_Y[BB][NN];
    __shared__ __align__(16) float sh_Qt[BB][NN];
    __shared__ __align__(16) float sh_G[BB][17];   // padded rows
    __shared__ __align__(16) float sh_T[BB][17];   // padded: t_l rows
    __shared__ __align__(16) float sh_pf[BB];
    __shared__ __align__(16) float sh_piv[BB];
    __shared__ __align__(16) float sh_u[NN];
    __shared__ int sh_kblk;

    const int tid  = threadIdx.x;
    const int lane = tid & 31;
    const int wid  = tid >> 5;
    const int r    = tid >> 2;      // owned row
    const int h    = tid & 3;       // col-slice id
    const int cbase = 32 * h;
    const int pos_base = NN * DD;

    // ---- init output: cond_probs = 0, positions = -1 ----
    {
        int n4 = out_size >> 2;
        float4* o4 = (float4*)out;
        for (int idx = tid; idx < n4; idx += TPB) {
            int base = idx * 4;
            float4 v;
            v.x = (base + 0 < pos_base) ? 0.0f : -1.0f;
            v.y = (base + 1 < pos_base) ? 0.0f : -1.0f;
            v.z = (base + 2 < pos_base) ? 0.0f : -1.0f;
            v.w = (base + 3 < pos_base) ? 0.0f : -1.0f;
            o4[idx] = v;
        }
        for (int idx = (n4 << 2) + tid; idx < out_size; idx += TPB)
            out[idx] = (idx < pos_base) ? 0.0f : -1.0f;
    }

    if (tid < NN) sh_u[tid] = uin[tid];
    if (tid == 0) sh_kblk = 0;
    if (tid < BB * 17) ((float*)sh_T)[tid] = 0.0f;

    // B slice = identity (16 packed f32x2 = 32 regs; must stay in RF)
    unsigned long long rb2[16];
#pragma unroll
    for (int m = 0; m < 16; ++m) {
        unsigned long long v = 0ULL;
        int c0 = cbase + 2 * m;
        if (c0 == r)          v = 0x000000003f800000ULL;
        else if (c0 + 1 == r) v = 0x3f80000000000000ULL;
        rb2[m] = v;
    }

    // ---- load UP block 0 ----
    {
        const float4* Pg = (const float4*)P;
        ((float4*)sh_UP[tid >> 5])[tid & 31] = Pg[tid];
    }
    __syncthreads();

    const bool write_pos = (pos_base + NN) <= out_size;

    // sampler state (only warp 0's copies matter)
    float ratio = 1.0f, cumul = 0.0f;
    int   k = 0;

    float4 nextUP, nextUP0;

#pragma unroll 1
    for (int m = 0; m < NBLK; ++m) {
        const int I0 = m * BB;

        // ---- prefetch next UP block into registers ----
        if (m + 1 < NBLK) {
            const float4* Pn = (const float4*)(P + (size_t)(I0 + BB) * NN);
            if (tid >= 32) nextUP = Pn[tid];
            if (tid >= 32 && tid < 64) nextUP0 = Pn[tid - 32];
        }

        // ---- phase1: Y = B * UP  (bounded unroll: keep live window small) ----
#pragma unroll 2
        for (int i = 0; i < BB; ++i) {
            const ulonglong2* u2 = (const ulonglong2*)(sh_UP[i] + cbase);
            unsigned long long a0 = 0, a1 = 0;
#pragma unroll
            for (int c = 0; c < 8; ++c) {
                ulonglong2 uv = u2[c];
                a0 = fma2(rb2[2 * c],     uv.x, a0);
                a1 = fma2(rb2[2 * c + 1], uv.y, a1);
            }
            float yp = (lo2(a0) + hi2(a0)) + (lo2(a1) + hi2(a1));
            yp += __shfl_xor_sync(0xffffffffu, yp, 1);
            yp += __shfl_xor_sync(0xffffffffu, yp, 2);
            if (h == 0) sh_Y[i][r] = yp;
        }
        __syncthreads();   // B1: Y ready

        // ---- phase2: G[i][l] = up_i . y_l (2 threads per entry) ----
        {
            int pr = tid >> 1;             // 0..255
            int gi = pr >> 4, gl = pr & 15;
            int half = tid & 1;
            const ulonglong2* ya = (const ulonglong2*)(sh_Y[gl]  + 64 * half);
            const ulonglong2* ua = (const ulonglong2*)(sh_UP[gi] + 64 * half);
            unsigned long long a0 = 0, a1 = 0;
#pragma unroll 4
            for (int c = 0; c < 16; ++c) {
                ulonglong2 yv = ya[c], uv = ua[c];
                a0 = fma2(yv.x, uv.x, a0);
                a1 = fma2(yv.y, uv.y, a1);
            }
            float g = (lo2(a0) + hi2(a0)) + (lo2(a1) + hi2(a1));
            g += __shfl_xor_sync(0xffffffffu, g, 1);
            if (half == 0) sh_G[gi][gl] = g;
        }
        __syncthreads();   // B2: G ready

        if (wid == 0) {
            // ---- warp-0 recursion, SMEM-resident state ----
            float pivreg = 0.0f;   // lane l: pivinv_l
#pragma unroll 1
            for (int j = 0; j < BB; ++j) {
                float f = 0.0f;
                if (lane < j) {
#pragma unroll
                    for (int e = 0; e < BB; ++e)
                        f += sh_G[j][e] * sh_T[lane][e];
                }
                float pf = pivreg * f;
                float rp = pf * f;
                rp += __shfl_xor_sync(0xffffffffu, rp, 8);
                rp += __shfl_xor_sync(0xffffffffu, rp, 4);
                rp += __shfl_xor_sync(0xffffffffu, rp, 2);
                rp += __shfl_xor_sync(0xffffffffu, rp, 1);
                float red = sh_G[j][j] + rp;

                int iglob = I0 + j;
                bool active = (k < NN);
                float s = 1.0f - red;
                int last_allowed = DD - NN + k;
                float p  = -(s - 1.0f) * ratio;
                float uk = sh_u[k < NN ? k : NN - 1];
                bool occupy = active &&
                              (((cumul + p) >= uk) || (iglob == last_allowed));
                float pivot = occupy ? (s - 1.0f) : s;
                if (fabsf(pivot) < TINYF) pivot = TINYF;
                float pivinv = active ? (1.0f / pivot) : 0.0f;

                if (lane == j) pivreg = pivinv;
                if (lane == 0) {
                    sh_piv[j] = pivinv;
                    if (active) out[k * DD + iglob] = p;
                    if (occupy && write_pos) out[pos_base + k] = (float)iglob;
                }
                if (occupy)      { ratio = 1.0f; cumul = 0.0f; ++k; }
                else if (active) { ratio *= s;  cumul += p; }

                if (lane < BB) sh_pf[lane] = pf;
                __syncwarp();

                if (lane < BB) {
                    float tv = (lane == j) ? 1.0f : 0.0f;
#pragma unroll
                    for (int l = 0; l < BB; ++l)
                        tv += sh_pf[l] * sh_T[l][lane];
                    sh_T[j][lane] = tv;
                }
                __syncwarp();
            }
            if (lane == 0) sh_kblk = k;
        } else {
            // ---- warps 1..15: stage next UP block (overlaps recursion) ----
            if (m + 1 < NBLK) {
                ((float4*)sh_UP[tid >> 5])[tid & 31] = nextUP;
                if (tid < 64) {
                    int p0 = tid - 32;
                    ((float4*)sh_UP[p0 >> 5])[p0 & 31] = nextUP0;
                }
            }
        }
        __syncthreads();   // B3: T/piv/kblk ready; next UP staged

        if (sh_kblk == NN) break;

        // ---- phaseQ: Q[j][r] = sum_l T[j][l] * Y[l][r] ----
        {
            int qj = tid >> 5, r4 = tid & 31;
            float4 a = make_float4(0.f, 0.f, 0.f, 0.f);
#pragma unroll 4
            for (int l = 0; l < BB; ++l) {
                float t = sh_T[qj][l];
                float4 yv = ((const float4*)sh_Y[l])[r4];
                a.x += t * yv.x; a.y += t * yv.y;
                a.z += t * yv.z; a.w += t * yv.w;
            }
            ((float4*)sh_Qt[qj])[r4] = a;
        }
        __syncthreads();   // B4: Q ready

        // ---- phase4: B += Q diag(piv) Q^T (bounded unroll) ----
#pragma unroll 2
        for (int j = 0; j < BB; ++j) {
            float qs = sh_Qt[j][r] * sh_piv[j];
            unsigned long long s2 = pack2(qs, qs);
            const ulonglong2* q2 = (const ulonglong2*)(sh_Qt[j] + cbase);
#pragma unroll
            for (int c = 0; c < 8; ++c) {
                ulonglong2 qv = q2[c];
                rb2[2 * c]     = fma2(s2, qv.x, rb2[2 * c]);
                rb2[2 * c + 1] = fma2(s2, qv.y, rb2[2 * c + 1]);
            }
        }
        // no end barrier: next phase1 reads sh_UP / writes sh_Y only.
    }
}

extern "C" void kernel_launch(void* const* d_in, const int* in_sizes, int n_in,
                              void* d_out, int out_size)
{
    const float* P = (const float*)d_in[0];   // (512, 128) row-major
    const float* u = (const float*)d_in[1];   // (128,)
    float* out = (float*)d_out;
    slater_sampler_kernel<<<1, TPB>>>(P, u, out, out_size);
}

// round 9
// speedup vs baseline: 2.1291x; 2.1291x over previous
#include <cuda_runtime.h>

#define DD 512
#define NN 128
#define TPB 256
#define BB 16
#define NBLK (DD / BB)
#define TINYF 1e-30f

// ---- packed f32x2 helpers (Blackwell FFMA2) ----
__device__ __forceinline__ unsigned long long fma2(unsigned long long a,
                                                   unsigned long long b,
                                                   unsigned long long c) {
    unsigned long long d;
    asm("fma.rn.f32x2 %0, %1, %2, %3;" : "=l"(d) : "l"(a), "l"(b), "l"(c));
    return d;
}
__device__ __forceinline__ float lo2(unsigned long long v) {
    return __uint_as_float((unsigned)v);
}
__device__ __forceinline__ float hi2(unsigned long long v) {
    return __uint_as_float((unsigned)(v >> 32));
}
__device__ __forceinline__ unsigned long long pack2(float x, float y) {
    unsigned long long d;
    asm("mov.b64 %0, {%1, %2};" : "=l"(d) : "f"(x), "f"(y));
    return d;
}
__device__ __forceinline__ void cp_async16(void* smem, const void* gmem) {
    unsigned saddr = (unsigned)__cvta_generic_to_shared(smem);
    asm volatile("cp.async.cg.shared.global [%0], [%1], 16;"
                 :: "r"(saddr), "l"(gmem));
}

// Blocked Woodbury sampler, b=16, 256 THREADS (reg cap 256 -> rb2 cannot
// spill; rounds 6-8 died to the 128-reg cap of 512-thread blocks).
// Thread t: row r = t>>1, col slice [64h, 64h+64), h = t&1, 32 packed f32x2.
// Next UP block staged by cp.async into a double buffer (no prefetch regs).
__global__ __launch_bounds__(TPB, 1)
void slater_sampler_kernel(const float* __restrict__ P,
                           const float* __restrict__ uin,
                           float* __restrict__ out,
                           int out_size)
{
    __shared__ __align__(16) float sh_UPD[2][BB][NN];
    __shared__ __align__(16) float sh_Y[BB][NN];
    __shared__ __align__(16) float sh_Qt[BB][NN];
    __shared__ __align__(16) float sh_G[BB][17];
    __shared__ __align__(16) float sh_T[BB][17];
    __shared__ __align__(16) float sh_pf[BB];
    __shared__ __align__(16) float sh_piv[BB];
    __shared__ __align__(16) float sh_u[NN];
    __shared__ int sh_kblk;

    const int tid  = threadIdx.x;
    const int lane = tid & 31;
    const int wid  = tid >> 5;
    const int r    = tid >> 1;      // owned row
    const int h    = tid & 1;       // col-slice id
    const int cbase = 64 * h;
    const int pos_base = NN * DD;

    // ---- init output: cond_probs = 0, positions = -1 ----
    {
        int n4 = out_size >> 2;
        float4* o4 = (float4*)out;
        for (int idx = tid; idx < n4; idx += TPB) {
            int base = idx * 4;
            float4 v;
            v.x = (base + 0 < pos_base) ? 0.0f : -1.0f;
            v.y = (base + 1 < pos_base) ? 0.0f : -1.0f;
            v.z = (base + 2 < pos_base) ? 0.0f : -1.0f;
            v.w = (base + 3 < pos_base) ? 0.0f : -1.0f;
            o4[idx] = v;
        }
        for (int idx = (n4 << 2) + tid; idx < out_size; idx += TPB)
            out[idx] = (idx < pos_base) ? 0.0f : -1.0f;
    }

    if (tid < NN) sh_u[tid] = uin[tid];
    if (tid == 0) sh_kblk = 0;
    for (int idx = tid; idx < BB * 17; idx += TPB) ((float*)sh_T)[idx] = 0.0f;

    // B slice = identity: 32 packed f32x2 = 64 regs (under the 256-reg cap)
    unsigned long long rb2[32];
#pragma unroll
    for (int m = 0; m < 32; ++m) {
        unsigned long long v = 0ULL;
        int c0 = cbase + 2 * m;
        if (c0 == r)          v = 0x000000003f800000ULL;
        else if (c0 + 1 == r) v = 0x3f80000000000000ULL;
        rb2[m] = v;
    }

    // ---- load UP block 0 (2048 floats = 512 float4, 2 per thread) ----
    {
        const float4* Pg = (const float4*)P;
        float4* dst = (float4*)sh_UPD[0];
        dst[tid]       = Pg[tid];
        dst[tid + 256] = Pg[tid + 256];
    }
    __syncthreads();

    const bool write_pos = (pos_base + NN) <= out_size;

    // sampler state (only warp 0's copies matter)
    float ratio = 1.0f, cumul = 0.0f;
    int   k = 0;

#pragma unroll 1
    for (int m = 0; m < NBLK; ++m) {
        const int I0 = m * BB;
        const int buf = m & 1;
        const float (*sh_UP)[NN] = sh_UPD[buf];

        // ---- stage next UP block via cp.async (no registers held) ----
        if (m + 1 < NBLK) {
            const float* src = P + (size_t)(I0 + BB) * NN;
            float* dst = (float*)sh_UPD[buf ^ 1];
            cp_async16(dst + tid * 4,         src + tid * 4);
            cp_async16(dst + (tid + 256) * 4, src + (tid + 256) * 4);
            asm volatile("cp.async.commit_group;");
        }

        // ---- phase1: Y = B * UP ----
#pragma unroll 2
        for (int i = 0; i < BB; ++i) {
            const ulonglong2* u2 = (const ulonglong2*)(sh_UP[i] + cbase);
            unsigned long long a0 = 0, a1 = 0, a2 = 0, a3 = 0;
#pragma unroll
            for (int c = 0; c < 8; ++c) {
                ulonglong2 va = u2[2 * c];
                ulonglong2 vb = u2[2 * c + 1];
                a0 = fma2(rb2[4 * c + 0], va.x, a0);
                a1 = fma2(rb2[4 * c + 1], va.y, a1);
                a2 = fma2(rb2[4 * c + 2], vb.x, a2);
                a3 = fma2(rb2[4 * c + 3], vb.y, a3);
            }
            float yp = ((lo2(a0) + hi2(a0)) + (lo2(a1) + hi2(a1)))
                     + ((lo2(a2) + hi2(a2)) + (lo2(a3) + hi2(a3)));
            yp += __shfl_xor_sync(0xffffffffu, yp, 1);
            if (h == 0) sh_Y[i][r] = yp;
        }
        __syncthreads();   // B1: Y ready

        // ---- phase2: G[gi][gl] = up_gi . y_gl (one thread per entry) ----
        {
            int gi = tid >> 4, gl = tid & 15;
            const ulonglong2* ya = (const ulonglong2*)sh_Y[gl];
            const ulonglong2* ua = (const ulonglong2*)sh_UP[gi];
            unsigned long long a0 = 0, a1 = 0;
#pragma unroll 8
            for (int c = 0; c < 32; ++c) {
                ulonglong2 yv = ya[c], uv = ua[c];
                a0 = fma2(yv.x, uv.x, a0);
                a1 = fma2(yv.y, uv.y, a1);
            }
            sh_G[gi][gl] = (lo2(a0) + hi2(a0)) + (lo2(a1) + hi2(a1));
        }
        __syncthreads();   // B2: G ready

        if (wid == 0) {
            // ---- warp-0 recursion, SMEM-resident state ----
            float pivreg = 0.0f;   // lane l: pivinv_l
#pragma unroll 1
            for (int j = 0; j < BB; ++j) {
                float f = 0.0f;
                if (lane < j) {
#pragma unroll
                    for (int e = 0; e < BB; ++e)
                        f += sh_G[j][e] * sh_T[lane][e];
                }
                float pf = pivreg * f;
                float rp = pf * f;
                rp += __shfl_xor_sync(0xffffffffu, rp, 8);
                rp += __shfl_xor_sync(0xffffffffu, rp, 4);
                rp += __shfl_xor_sync(0xffffffffu, rp, 2);
                rp += __shfl_xor_sync(0xffffffffu, rp, 1);
                float red = sh_G[j][j] + rp;

                int iglob = I0 + j;
                bool active = (k < NN);
                float s = 1.0f - red;
                int last_allowed = DD - NN + k;
                float p  = -(s - 1.0f) * ratio;
                float uk = sh_u[k < NN ? k : NN - 1];
                bool occupy = active &&
                              (((cumul + p) >= uk) || (iglob == last_allowed));
                float pivot = occupy ? (s - 1.0f) : s;
                if (fabsf(pivot) < TINYF) pivot = TINYF;
                float pivinv = active ? (1.0f / pivot) : 0.0f;

                if (lane == j) pivreg = pivinv;
                if (lane == 0) {
                    sh_piv[j] = pivinv;
                    if (active) out[k * DD + iglob] = p;
                    if (occupy && write_pos) out[pos_base + k] = (float)iglob;
                }
                if (occupy)      { ratio = 1.0f; cumul = 0.0f; ++k; }
                else if (active) { ratio *= s;  cumul += p; }

                if (lane < BB) sh_pf[lane] = pf;
                __syncwarp();

                if (lane < BB) {
                    float tv = (lane == j) ? 1.0f : 0.0f;
#pragma unroll
                    for (int l = 0; l < BB; ++l)
                        tv += sh_pf[l] * sh_T[l][lane];
                    sh_T[j][lane] = tv;
                }
                __syncwarp();
            }
            if (lane == 0) sh_kblk = k;
        }
        __syncthreads();   // B3: T/piv/kblk ready

        if (sh_kblk == NN) break;

        // ---- phaseQ: Q[qj][c8..c8+8) = sum_l T[qj][l] * Y[l][...] ----
        {
            int qj = tid >> 4, c8 = (tid & 15) * 8;
            float4 a = make_float4(0.f, 0.f, 0.f, 0.f);
            float4 b = make_float4(0.f, 0.f, 0.f, 0.f);
#pragma unroll 4
            for (int l = 0; l < BB; ++l) {
                float t = sh_T[qj][l];
                const float4* yv = (const float4*)(sh_Y[l] + c8);
                float4 y0 = yv[0], y1 = yv[1];
                a.x += t * y0.x; a.y += t * y0.y;
                a.z += t * y0.z; a.w += t * y0.w;
                b.x += t * y1.x; b.y += t * y1.y;
                b.z += t * y1.z; b.w += t * y1.w;
            }
            float4* qd = (float4*)(sh_Qt[qj] + c8);
            qd[0] = a; qd[1] = b;
        }
        __syncthreads();   // B4: Q ready

        // ---- phase4: B += Q diag(piv) Q^T ----
#pragma unroll 2
        for (int j = 0; j < BB; ++j) {
            float qs = sh_Qt[j][r] * sh_piv[j];
            unsigned long long s2 = pack2(qs, qs);
            const ulonglong2* q2 = (const ulonglong2*)(sh_Qt[j] + cbase);
#pragma unroll
            for (int c = 0; c < 8; ++c) {
                ulonglong2 va = q2[2 * c];
                ulonglong2 vb = q2[2 * c + 1];
                rb2[4 * c + 0] = fma2(s2, va.x, rb2[4 * c + 0]);
                rb2[4 * c + 1] = fma2(s2, va.y, rb2[4 * c + 1]);
                rb2[4 * c + 2] = fma2(s2, vb.x, rb2[4 * c + 2]);
                rb2[4 * c + 3] = fma2(s2, vb.y, rb2[4 * c + 3]);
            }
        }

        asm volatile("cp.async.wait_group 0;");
        __syncthreads();   // B5: next UP staged, phase4 reads done
    }
}

extern "C" void kernel_launch(void* const* d_in, const int* in_sizes, int n_in,
                              void* d_out, int out_size)
{
    const float* P = (const float*)d_in[0];   // (512, 128) row-major
    const float* u = (const float*)d_in[1];   // (128,)
    float* out = (float*)d_out;
    slater_sampler_kernel<<<1, TPB>>>(P, u, out, out_size);
}

// round 10
// speedup vs baseline: 2.3252x; 1.0921x over previous
#include <cuda_runtime.h>

#define DD 512
#define NN 128
#define TPB 288
#define BB 16
#define NBLK 32
#define TINYF 1e-30f

// ---- packed f32x2 helpers (Blackwell FFMA2) ----
__device__ __forceinline__ unsigned long long fma2(unsigned long long a,
                                                   unsigned long long b,
                                                   unsigned long long c) {
    unsigned long long d;
    asm("fma.rn.f32x2 %0, %1, %2, %3;" : "=l"(d) : "l"(a), "l"(b), "l"(c));
    return d;
}
__device__ __forceinline__ float lo2(unsigned long long v) {
    return __uint_as_float((unsigned)v);
}
__device__ __forceinline__ float hi2(unsigned long long v) {
    return __uint_as_float((unsigned)(v >> 32));
}
__device__ __forceinline__ unsigned long long pack2(float x, float y) {
    unsigned long long d;
    asm("mov.b64 %0, {%1, %2};" : "=l"(d) : "f"(x), "f"(y));
    return d;
}
__device__ __forceinline__ void cp_async16(void* smem, const void* gmem) {
    unsigned saddr = (unsigned)__cvta_generic_to_shared(smem);
    asm volatile("cp.async.cg.shared.global [%0], [%1], 16;"
                 :: "r"(saddr), "l"(gmem));
}

// Pipelined blocked Woodbury sampler, b=16, 288 threads.
//
// Warp 0: scalar/recursion warp (owns NO B rows).
// Warps 1-8 (256 threads): B in registers; thread bt=tid-32 owns row
//   r=bt>>1, cols [64h,64h+64) as rb2[32].
//
// Pipeline per block m:
//   PARALLEL:  warp 0 runs the sampling recursion on G_m (produces T, piv,
//              outputs, k);  warps 1-8 concurrently do
//              fold: B += Y_{m-1} M_{m-1} Y_{m-1}^T   (via W = Y M)
//              Zraw_{m+1} = B UP_{m+1}
//   SERIAL (prep m+1):
//     stage1: C = Y_m^T UP_{m+1};  Graw = UP_{m+1}^T Zraw;  M_m = T^T d(piv) T
//     stage2: E = M_m C
//     stage3: G_{m+1} = Graw + C^T E;  Y_{m+1} = Zraw + Y_m E;
//             cp.async UP_{m+2}
__global__ __launch_bounds__(TPB, 1)
void slater_sampler_kernel(const float* __restrict__ P,
                           const float* __restrict__ uin,
                           float* __restrict__ out,
                           int out_size)
{
    __shared__ __align__(16) float sh_UP[2][BB][NN];
    __shared__ __align__(16) float sh_Y[2][BB][NN];
    __shared__ __align__(16) float sh_Z[BB][NN];
    __shared__ __align__(16) float sh_G[BB][BB];
    __shared__ __align__(16) float sh_T[BB][BB];
    __shared__ __align__(16) float sh_C[BB][BB];
    __shared__ __align__(16) float sh_E[BB][BB];
    __shared__ __align__(16) float sh_M[BB][BB];
    __shared__ __align__(16) float sh_piv[BB];
    __shared__ __align__(16) float sh_u[NN];
    __shared__ int sh_kblk;

    const int tid  = threadIdx.x;
    const int lane = tid & 31;
    const int wid  = tid >> 5;
    const int bt   = tid - 32;           // B-thread index (wid > 0)
    const int r    = bt >> 1;
    const int h    = bt & 1;
    const int cbase = 64 * h;
    const int pos_base = NN * DD;

    // ---- init output: cond_probs = 0, positions = -1 ----
    {
        int n4 = out_size >> 2;
        float4* o4 = (float4*)out;
        for (int idx = tid; idx < n4; idx += TPB) {
            int base = idx * 4;
            float4 v;
            v.x = (base + 0 < pos_base) ? 0.0f : -1.0f;
            v.y = (base + 1 < pos_base) ? 0.0f : -1.0f;
            v.z = (base + 2 < pos_base) ? 0.0f : -1.0f;
            v.w = (base + 3 < pos_base) ? 0.0f : -1.0f;
            o4[idx] = v;
        }
        for (int idx = (n4 << 2) + tid; idx < out_size; idx += TPB)
            out[idx] = (idx < pos_base) ? 0.0f : -1.0f;
    }

    if (tid < NN) sh_u[tid] = uin[tid];
    if (tid == 0) sh_kblk = 0;

    // B slice = identity (warps 1-8 only): rb2[32] = 64 regs, cap 227 -> safe
    unsigned long long rb2[32];
    if (wid > 0) {
#pragma unroll
        for (int q = 0; q < 32; ++q) {
            unsigned long long v = 0ULL;
            int c0 = cbase + 2 * q;
            if (c0 == r)          v = 0x000000003f800000ULL;
            else if (c0 + 1 == r) v = 0x3f80000000000000ULL;
            rb2[q] = v;
        }
    }

    // ---- preload UP_0, UP_1 (contiguous 1024 float4); Y_0 = UP_0 ----
    {
        const float4* Pg = (const float4*)P;
        float4* upf = (float4*)sh_UP;
        float4* yf  = (float4*)sh_Y[0];
        for (int idx = tid; idx < 1024; idx += TPB) {
            float4 v = Pg[idx];
            upf[idx] = v;
            if (idx < 512) yf[idx] = v;
        }
    }
    __syncthreads();

    // ---- G_0[a][b] = up_a . up_b ----
    if (tid < 256) {
        int a = tid >> 4, b = tid & 15;
        const ulonglong2* x2 = (const ulonglong2*)sh_UP[0][a];
        const ulonglong2* y2 = (const ulonglong2*)sh_UP[0][b];
        unsigned long long a0 = 0, a1 = 0;
#pragma unroll 8
        for (int c = 0; c < 32; ++c) {
            ulonglong2 xv = x2[c], yv = y2[c];
            a0 = fma2(xv.x, yv.x, a0);
            a1 = fma2(xv.y, yv.y, a1);
        }
        sh_G[a][b] = (lo2(a0) + hi2(a0)) + (lo2(a1) + hi2(a1));
    }
    __syncthreads();

    const bool write_pos = (pos_base + NN) <= out_size;

    // warp-0 sampler state (redundant across warp-0 lanes)
    float ratio = 1.0f, cumul = 0.0f;
    int   k = 0;

#pragma unroll 1
    for (int m = 0; m < NBLK; ++m) {
        // ================= PARALLEL PHASE =================
        if (wid == 0) {
            // ---- recursion on G_m (right-looking, register-resident) ----
            const int la = lane & 15;
            float Grow[BB];
            {
                const float4* g4 = (const float4*)sh_G[la];
                float4 a = g4[0], b = g4[1], c = g4[2], d = g4[3];
                Grow[0]=a.x; Grow[1]=a.y; Grow[2]=a.z; Grow[3]=a.w;
                Grow[4]=b.x; Grow[5]=b.y; Grow[6]=b.z; Grow[7]=b.w;
                Grow[8]=c.x; Grow[9]=c.y; Grow[10]=c.z; Grow[11]=c.w;
                Grow[12]=d.x; Grow[13]=d.y; Grow[14]=d.z; Grow[15]=d.w;
            }
            float tvec[BB];
#pragma unroll
            for (int e = 0; e < BB; ++e) tvec[e] = 0.0f;
            float racc = 0.0f;

#pragma unroll
            for (int j = 0; j < BB; ++j) {
                float red = __shfl_sync(0xffffffffu, Grow[j] + racc, j);
                int iglob = m * BB + j;
                bool active = (k < NN);
                float s = 1.0f - red;
                int last_allowed = DD - NN + k;
                float p  = -(s - 1.0f) * ratio;
                float uk = sh_u[k < NN ? k : NN - 1];
                bool occupy = active &&
                              (((cumul + p) >= uk) || (iglob == last_allowed));
                float pivot = occupy ? (s - 1.0f) : s;
                if (fabsf(pivot) < TINYF) pivot = TINYF;
                float pivinv = active ? (1.0f / pivot) : 0.0f;

                if (lane == 0) {
                    sh_piv[j] = pivinv;
                    if (active) out[k * DD + iglob] = p;
                    if (occupy && write_pos) out[pos_base + k] = (float)iglob;
                }
                if (occupy)      { ratio = 1.0f; cumul = 0.0f; ++k; }
                else if (active) { ratio *= s;  cumul += p; }

                // lane j publishes t_j = e_j + tvec_j
                if (lane == j) {
                    float4* t4 = (float4*)sh_T[j];
                    t4[0] = make_float4(tvec[0] + (j==0 ?1.f:0.f),
                                        tvec[1] + (j==1 ?1.f:0.f),
                                        tvec[2] + (j==2 ?1.f:0.f),
                                        tvec[3] + (j==3 ?1.f:0.f));
                    t4[1] = make_float4(tvec[4] + (j==4 ?1.f:0.f),
                                        tvec[5] + (j==5 ?1.f:0.f),
                                        tvec[6] + (j==6 ?1.f:0.f),
                                        tvec[7] + (j==7 ?1.f:0.f));
                    t4[2] = make_float4(tvec[8] + (j==8 ?1.f:0.f),
                                        tvec[9] + (j==9 ?1.f:0.f),
                                        tvec[10]+ (j==10?1.f:0.f),
                                        tvec[11]+ (j==11?1.f:0.f));
                    t4[3] = make_float4(tvec[12]+ (j==12?1.f:0.f),
                                        tvec[13]+ (j==13?1.f:0.f),
                                        tvec[14]+ (j==14?1.f:0.f),
                                        tvec[15]+ (j==15?1.f:0.f));
                }
                __syncwarp();

                const float4* t4 = (const float4*)sh_T[j];
                float4 ta = t4[0], tb = t4[1], tc = t4[2], td = t4[3];
                float f = (((Grow[0]*ta.x + Grow[1]*ta.y) + (Grow[2]*ta.z + Grow[3]*ta.w))
                        +  ((Grow[4]*tb.x + Grow[5]*tb.y) + (Grow[6]*tb.z + Grow[7]*tb.w)))
                        + (((Grow[8]*tc.x + Grow[9]*tc.y) + (Grow[10]*tc.z + Grow[11]*tc.w))
                        +  ((Grow[12]*td.x + Grow[13]*td.y) + (Grow[14]*td.z + Grow[15]*td.w)));
                float pf = pivinv * f;
                racc += pf * f;
                tvec[0]+=pf*ta.x; tvec[1]+=pf*ta.y; tvec[2]+=pf*ta.z; tvec[3]+=pf*ta.w;
                tvec[4]+=pf*tb.x; tvec[5]+=pf*tb.y; tvec[6]+=pf*tb.z; tvec[7]+=pf*tb.w;
                tvec[8]+=pf*tc.x; tvec[9]+=pf*tc.y; tvec[10]+=pf*tc.z; tvec[11]+=pf*tc.w;
                tvec[12]+=pf*td.x; tvec[13]+=pf*td.y; tvec[14]+=pf*td.z; tvec[15]+=pf*td.w;
            }
            if (lane == 0) sh_kblk = k;
        } else {
            // ---- warps 1-8: fold(m-1) then Zraw_{m+1} ----
            if (m > 0) {
                asm volatile("cp.async.wait_group 0;");  // UP_{m+1} resident
            }
            if (m > 0) {
                const float (*Yp)[NN] = sh_Y[(m - 1) & 1];
                float yl[BB];
#pragma unroll
                for (int l = 0; l < BB; ++l) yl[l] = Yp[l][r];
                float W[BB];
#pragma unroll
                for (int j = 0; j < BB; ++j) W[j] = 0.0f;
#pragma unroll 4
                for (int l = 0; l < BB; ++l) {
                    const float4* m4 = (const float4*)sh_M[l];
                    float4 m0 = m4[0], m1 = m4[1], m2 = m4[2], m3 = m4[3];
                    float y = yl[l];
                    W[0]+=y*m0.x; W[1]+=y*m0.y; W[2]+=y*m0.z; W[3]+=y*m0.w;
                    W[4]+=y*m1.x; W[5]+=y*m1.y; W[6]+=y*m1.z; W[7]+=y*m1.w;
                    W[8]+=y*m2.x; W[9]+=y*m2.y; W[10]+=y*m2.z; W[11]+=y*m2.w;
                    W[12]+=y*m3.x; W[13]+=y*m3.y; W[14]+=y*m3.z; W[15]+=y*m3.w;
                }
                // B += W_j * Y_{m-1}[j][cols]
#pragma unroll 2
                for (int j = 0; j < BB; ++j) {
                    unsigned long long s2 = pack2(W[j], W[j]);
                    const ulonglong2* q2 = (const ulonglong2*)(Yp[j] + cbase);
#pragma unroll
                    for (int c = 0; c < 8; ++c) {
                        ulonglong2 va = q2[2 * c];
                        ulonglong2 vb = q2[2 * c + 1];
                        rb2[4*c+0] = fma2(s2, va.x, rb2[4*c+0]);
                        rb2[4*c+1] = fma2(s2, va.y, rb2[4*c+1]);
                        rb2[4*c+2] = fma2(s2, vb.x, rb2[4*c+2]);
                        rb2[4*c+3] = fma2(s2, vb.y, rb2[4*c+3]);
                    }
                }
            }
            if (m + 1 < NBLK) {
                const float (*Un)[NN] = sh_UP[(m + 1) & 1];
#pragma unroll 2
                for (int i = 0; i < BB; ++i) {
                    const ulonglong2* u2 = (const ulonglong2*)(Un[i] + cbase);
                    unsigned long long a0 = 0, a1 = 0, a2 = 0, a3 = 0;
#pragma unroll
                    for (int c = 0; c < 8; ++c) {
                        ulonglong2 va = u2[2 * c];
                        ulonglong2 vb = u2[2 * c + 1];
                        a0 = fma2(rb2[4*c+0], va.x, a0);
                        a1 = fma2(rb2[4*c+1], va.y, a1);
                        a2 = fma2(rb2[4*c+2], vb.x, a2);
                        a3 = fma2(rb2[4*c+3], vb.y, a3);
                    }
                    float zp = ((lo2(a0)+hi2(a0)) + (lo2(a1)+hi2(a1)))
                             + ((lo2(a2)+hi2(a2)) + (lo2(a3)+hi2(a3)));
                    zp += __shfl_xor_sync(0xffffffffu, zp, 1);
                    if (h == 0) sh_Z[i][r] = zp;
                }
            }
        }
        __syncthreads();

        if (sh_kblk == NN || m + 1 == NBLK) break;

        // ================= SERIAL PHASE (prep m+1) =================
        const float (*Un)[NN] = sh_UP[(m + 1) & 1];
        const float (*Ym)[NN] = sh_Y[m & 1];

        // stage1: C[a][b] = Y_m[a].UP_{m+1}[b];  Graw -> sh_G;  M_m -> sh_M
        if (tid < 256) {
            int a = tid >> 4, b = tid & 15;
            {
                const ulonglong2* x2 = (const ulonglong2*)Ym[a];
                const ulonglong2* y2 = (const ulonglong2*)Un[b];
                unsigned long long a0 = 0, a1 = 0;
#pragma unroll 8
                for (int c = 0; c < 32; ++c) {
                    ulonglong2 xv = x2[c], yv = y2[c];
                    a0 = fma2(xv.x, yv.x, a0);
                    a1 = fma2(xv.y, yv.y, a1);
                }
                sh_C[a][b] = (lo2(a0)+hi2(a0)) + (lo2(a1)+hi2(a1));
            }
            {
                const ulonglong2* x2 = (const ulonglong2*)Un[a];
                const ulonglong2* y2 = (const ulonglong2*)sh_Z[b];
                unsigned long long a0 = 0, a1 = 0;
#pragma unroll 8
                for (int c = 0; c < 32; ++c) {
                    ulonglong2 xv = x2[c], yv = y2[c];
                    a0 = fma2(xv.x, yv.x, a0);
                    a1 = fma2(xv.y, yv.y, a1);
                }
                sh_G[a][b] = (lo2(a0)+hi2(a0)) + (lo2(a1)+hi2(a1));
            }
            {
                float acc = 0.0f;
#pragma unroll
                for (int j = 0; j < BB; ++j)
                    acc += sh_piv[j] * sh_T[j][a] * sh_T[j][b];
                sh_M[a][b] = acc;
            }
        }
        __syncthreads();

        // stage2: E = M C
        if (tid < 256) {
            int a = tid >> 4, b = tid & 15;
            float acc = 0.0f;
#pragma unroll
            for (int l = 0; l < BB; ++l)
                acc += sh_M[a][l] * sh_C[l][b];
            sh_E[a][b] = acc;
        }
        __syncthreads();

        // stage3: G += C^T E ;  Y_{m+1} = Zraw + Y_m E ;  prefetch UP_{m+2}
        if (tid < 256) {
            int a = tid >> 4, b = tid & 15;
            float acc = sh_G[a][b];
#pragma unroll
            for (int l = 0; l < BB; ++l)
                acc += sh_C[l][a] * sh_E[l][b];
            sh_G[a][b] = acc;
        }
        if (tid < 256) {
            int r2 = tid >> 1, ib = 8 * (tid & 1);
            float yl2[BB];
#pragma unroll
            for (int l = 0; l < BB; ++l) yl2[l] = Ym[l][r2];
            float (*Yn)[NN] = sh_Y[(m + 1) & 1];
#pragma unroll
            for (int ii = 0; ii < 8; ++ii) {
                int i = ib + ii;
                float acc = sh_Z[i][r2];
#pragma unroll
                for (int l = 0; l < BB; ++l)
                    acc += yl2[l] * sh_E[l][i];
                Yn[i][r2] = acc;
            }
        }
        if (m + 2 < NBLK && wid > 0) {
            // UP_{m+2} -> buffer (m&1); issued by B-threads, waited next block
            float* dst = (float*)sh_UP[m & 1];
            const float* src = P + (size_t)(m + 2) * BB * NN;
            cp_async16((float4*)dst + bt,       (const float4*)src + bt);
            cp_async16((float4*)dst + bt + 256, (const float4*)src + bt + 256);
            asm volatile("cp.async.commit_group;");
        }
        __syncthreads();
    }
}

extern "C" void kernel_launch(void* const* d_in, const int* in_sizes, int n_in,
                              void* d_out, int out_size)
{
    const float* P = (const float*)d_in[0];   // (512, 128) row-major
    const float* u = (const float*)d_in[1];   // (128,)
    float* out = (float*)d_out;
    slater_sampler_kernel<<<1, TPB>>>(P, u, out, out_size);
}